// round 10
// baseline (speedup 1.0000x reference)
#include <cuda_runtime.h>
#include <cuda_bf16.h>
#include <cuda_fp16.h>
#include <math.h>

#define NU 100000
#define NI 50000
#define DIMV 64
#define RK 5
#define NNZE 2000000
#define NUID 2048
#define NIID 4096
#define NBU 782   // ceil(NU/128)
#define NBI 391   // ceil(NI/128)

// ---------------- device scratch (no allocations allowed) ----------------
__device__ __align__(16) float g_Eu0[NU*DIMV];
__device__ __align__(16) float g_Ei0[NI*DIMV];
__device__ __align__(16) float g_Zu1[NU*DIMV];
__device__ __align__(16) float g_Zi1[NI*DIMV];
__device__ __align__(16) float g_Eu [NU*DIMV];
__device__ __align__(16) float g_Ei [NI*DIMV];
__device__ __align__(16) __nv_bfloat16 g_E0bfU[NU*DIMV];
__device__ __align__(16) __nv_bfloat16 g_E0bfI[NI*DIMV];
__device__ __align__(16) __nv_bfloat16 g_Z1bfU[NU*DIMV];
__device__ __align__(16) __nv_bfloat16 g_Z1bfI[NI*DIMV];
__device__ __align__(16) __nv_bfloat16 g_EbfU[NU*DIMV];
__device__ __align__(16) __nv_bfloat16 g_EbfI[NI*DIMV];
__device__ __align__(16) float g_GselU[NUID*DIMV];
__device__ __align__(16) float g_GselI[NIID*DIMV];
__device__ __align__(16) __nv_bfloat16 g_AbfU[NUID*DIMV];
__device__ __align__(16) __nv_bfloat16 g_AbfI[NIID*DIMV];
__device__ float g_P1[RK*DIMV];
__device__ float g_P2[RK*DIMV];
__device__ int   g_rcnt[NU];
__device__ int   g_rbase[NU];
__device__ int   g_ccnt[NI];
__device__ int   g_cbase[NI];
__device__ __align__(16) int2 g_redge[NNZE];   // (col, val_bits)
__device__ __align__(16) int2 g_cedge[NNZE];   // (row, val_bits)
__device__ int   g_bsU[128];
__device__ int   g_bsI[128];
__device__ float g_sumU[NUID];
__device__ float g_sumI[NIID];
__device__ float g_scal[8];

__device__ __forceinline__ uint2 pack_bf4(float4 v){
    __nv_bfloat162 p0 = __floats2bfloat162_rn(v.x, v.y);
    __nv_bfloat162 p1 = __floats2bfloat162_rn(v.z, v.w);
    uint2 r;
    r.x = *(unsigned*)&p0;
    r.y = *(unsigned*)&p1;
    return r;
}

// ---------------- kernels ----------------

// fused zero + E0 init (fp32 + bf16 copies)
__global__ void k_setup(const float4* __restrict__ ue, const float4* __restrict__ uep,
                        const float4* __restrict__ ie, const float4* __restrict__ iep,
                        float4* __restrict__ Eu0, float4* __restrict__ Ei0,
                        uint2* __restrict__ E0bfU, uint2* __restrict__ E0bfI,
                        int* rcnt,int* ccnt,
                        float* P1,float* P2,float* sumU,float* sumI,float* scal){
    int i = blockIdx.x*256 + threadIdx.x;
    if (i < NU*16){
        float4 a = ue[i], b = uep[i];
        float4 s = make_float4(a.x+b.x, a.y+b.y, a.z+b.z, a.w+b.w);
        Eu0[i] = s;
        E0bfU[i] = pack_bf4(s);
    } else if (i < (NU+NI)*16){
        int k = i - NU*16;
        float4 a = ie[k], b = iep[k];
        float4 s = make_float4(a.x+b.x, a.y+b.y, a.z+b.z, a.w+b.w);
        Ei0[k] = s;
        E0bfI[k] = pack_bf4(s);
    }
    if (i < NU) rcnt[i]=0;
    if (i < NI) ccnt[i]=0;
    if (i < NUID) sumU[i]=0.f;
    if (i < NIID) sumI[i]=0.f;
    if (i < RK*DIMV){ P1[i]=0.f; P2[i]=0.f; }
    if (i < 8) scal[i]=0.f;
}

__global__ void k_count(const int* __restrict__ rows, const int* __restrict__ cols,
                        int* rcnt, int* ccnt){
    int e = blockIdx.x*256 + threadIdx.x;
    if (e < NNZE){
        atomicAdd(&rcnt[rows[e]], 1);
        atomicAdd(&ccnt[cols[e]], 1);
    }
}

// fused U/I block scan: blocks 0..97 -> rcnt, 98..146 -> ccnt
__global__ void k_scanb(const int* __restrict__ rcnt, int* rbase, int* bsU,
                        const int* __restrict__ ccnt, int* cbase, int* bsI){
    __shared__ int sh[1024];
    const int* cnt; int* base; int* bsums; int n, b;
    if (blockIdx.x < 98){ cnt=rcnt; base=rbase; bsums=bsU; n=NU; b=blockIdx.x; }
    else                { cnt=ccnt; base=cbase; bsums=bsI; n=NI; b=blockIdx.x-98; }
    int i = b*1024 + threadIdx.x;
    int v = (i < n) ? cnt[i] : 0;
    sh[threadIdx.x] = v;
    __syncthreads();
    for (int off=1; off<1024; off<<=1){
        int t = (threadIdx.x >= off) ? sh[threadIdx.x-off] : 0;
        __syncthreads();
        sh[threadIdx.x] += t;
        __syncthreads();
    }
    if (i < n) base[i] = sh[threadIdx.x] - v;
    if (threadIdx.x == 1023) bsums[b] = sh[1023];
}

// fused top scan: threads 0..127 scan bsU(98), 128..255 scan bsI(49)
__global__ void k_scant(int* bsU, int* bsI){
    __shared__ int sh[256];
    int tid = threadIdx.x;
    int seg = tid >> 7, l = tid & 127;
    int nb = seg ? 49 : 98;
    int* arr = seg ? bsI : bsU;
    int v = (l < nb) ? arr[l] : 0;
    sh[tid] = v;
    __syncthreads();
    for (int off=1; off<128; off<<=1){
        int t = (l >= off) ? sh[tid-off] : 0;
        __syncthreads();
        sh[tid] += t;
        __syncthreads();
    }
    if (l < nb) arr[l] = sh[tid] - v;
}

__global__ void k_scana(int* rbase, const int* __restrict__ bsU,
                        int* cbase, const int* __restrict__ bsI){
    int* base; const int* bsums; int n, b;
    if (blockIdx.x < 98){ base=rbase; bsums=bsU; n=NU; b=blockIdx.x; }
    else                { base=cbase; bsums=bsI; n=NI; b=blockIdx.x-98; }
    int i = b*1024 + threadIdx.x;
    if (i < n) base[i] += bsums[b];
}

// destructive scatter: after this, rbase[r] = row_end (= start + cnt)
__global__ void k_scatter(const int* __restrict__ rows, const int* __restrict__ cols,
                          const float* __restrict__ vals,
                          int* rbase, int2* redge, int* cbase, int2* cedge){
    int e = blockIdx.x*256 + threadIdx.x;
    if (e < NNZE){
        int r = rows[e], c = cols[e];
        int vb = __float_as_int(vals[e]);
        int pr = atomicAdd(&rbase[r], 1);
        redge[pr] = make_int2(c, vb);
        int pc = atomicAdd(&cbase[c], 1);
        cedge[pc] = make_int2(r, vb);
    }
}

struct SpArgs {
    const int* base; const int* cnt; const int2* edges;
    const __nv_bfloat16* srcbf;
    const float* add0; const float* add1;
    float scale;
    float* dst; __nv_bfloat16* bdst;
    const float* img; const float* txt; float* outp;
    int nrows;
};

// merged U+I gather-style SpMM (bf16 gathers, fp32 accumulation).
// rows [0,NU) from args u, rows [NU,NU+NI) from args w. CTA=16 rows aligns
// to the U/I boundary (NU divisible by 16).
__global__ void k_spmm(SpArgs u, SpArgs w){
    int growl = blockIdx.x*16 + (threadIdx.x >> 4);
    SpArgs a = (growl < NU) ? u : w;
    int row = (growl < NU) ? growl : growl - NU;
    int lane = threadIdx.x & 15;
    if (row >= a.nrows) return;
    unsigned gmask = 0xffffu << (threadIdx.x & 16);
    int n = a.cnt[row];
    int s = a.base[row] - n;     // base was advanced to row_end by scatter
    float4 acc = make_float4(0.f,0.f,0.f,0.f);
    const uint2* s2 = (const uint2*)a.srcbf;
    int nb = n & ~15;
    for (int p = 0; p < nb; p += 16){
        int2 my = a.edges[s + p + lane];
        #pragma unroll
        for (int q=0;q<16;q++){
            int col = __shfl_sync(gmask, my.x, q, 16);
            float v = __int_as_float(__shfl_sync(gmask, my.y, q, 16));
            uint2 qv = s2[(size_t)col*16 + lane];
            float2 x = __bfloat1622float2(*(const __nv_bfloat162*)&qv.x);
            float2 y = __bfloat1622float2(*(const __nv_bfloat162*)&qv.y);
            acc.x = fmaf(v, x.x, acc.x);
            acc.y = fmaf(v, x.y, acc.y);
            acc.z = fmaf(v, y.x, acc.z);
            acc.w = fmaf(v, y.y, acc.w);
        }
    }
    int rem = n - nb;
    if (rem > 0){
        int2 my = (lane < rem) ? a.edges[s + nb + lane] : make_int2(0,0);
        for (int q=0;q<rem;q++){
            int col = __shfl_sync(gmask, my.x, q, 16);
            float v = __int_as_float(__shfl_sync(gmask, my.y, q, 16));
            uint2 qv = s2[(size_t)col*16 + lane];
            float2 x = __bfloat1622float2(*(const __nv_bfloat162*)&qv.x);
            float2 y = __bfloat1622float2(*(const __nv_bfloat162*)&qv.y);
            acc.x = fmaf(v, x.x, acc.x);
            acc.y = fmaf(v, x.y, acc.y);
            acc.z = fmaf(v, y.x, acc.z);
            acc.w = fmaf(v, y.y, acc.w);
        }
    }
    size_t o = (size_t)row*16 + lane;
    if (a.add0){ float4 t = ((const float4*)a.add0)[o]; acc.x+=t.x; acc.y+=t.y; acc.z+=t.z; acc.w+=t.w; }
    if (a.add1){ float4 t = ((const float4*)a.add1)[o]; acc.x+=t.x; acc.y+=t.y; acc.z+=t.z; acc.w+=t.w; }
    acc.x*=a.scale; acc.y*=a.scale; acc.z*=a.scale; acc.w*=a.scale;
    ((float4*)a.dst)[o] = acc;
    if (a.bdst) ((uint2*)a.bdst)[o] = pack_bf4(acc);
    if (a.outp){
        float4 a4 = ((const float4*)a.img)[o];
        float4 b4 = ((const float4*)a.txt)[o];
        float sa = a4.x*a4.x + a4.y*a4.y + a4.z*a4.z + a4.w*a4.w;
        float sb = b4.x*b4.x + b4.y*b4.y + b4.z*b4.z + b4.w*b4.w;
        #pragma unroll
        for (int off=8; off>0; off>>=1){
            sa += __shfl_xor_sync(gmask, sa, off, 16);
            sb += __shfl_xor_sync(gmask, sb, off, 16);
        }
        float na = fmaxf(sqrtf(sa), 1e-12f);
        float nb2 = fmaxf(sqrtf(sb), 1e-12f);
        float4 r;
        r.x = acc.x + 0.02f*(a4.x/na) + 0.02f*(b4.x/nb2);
        r.y = acc.y + 0.02f*(a4.y/na) + 0.02f*(b4.y/nb2);
        r.z = acc.z + 0.02f*(a4.z/na) + 0.02f*(b4.z/nb2);
        r.w = acc.w + 0.02f*(a4.w/na) + 0.02f*(b4.w/nb2);
        ((float4*)a.outp)[o] = r;
    }
}

// merged low-rank: blocks [0,128) -> P1 from (vt, Ei0+Zi1), [128,256) -> P2 from (ut, Eu0+Zu1)
__global__ void k_lowrank(const float* __restrict__ vt, const float* __restrict__ Ei0,
                          const float* __restrict__ Zi1, float* P1,
                          const float* __restrict__ ut, const float* __restrict__ Eu0,
                          const float* __restrict__ Zu1, float* P2){
    const float *fac, *A, *B; float* P; int n, blk;
    if (blockIdx.x < 128){ fac=vt; A=Ei0; B=Zi1; P=P1; n=NI; blk=blockIdx.x; }
    else                 { fac=ut; A=Eu0; B=Zu1; P=P2; n=NU; blk=blockIdx.x-128; }
    int d  = threadIdx.x & 63;
    int il = threadIdx.x >> 6;   // 0..3
    int chunk = (n + 127) / 128;
    int i0 = blk*chunk;
    int i1 = min(i0 + chunk, n);
    float acc[RK];
    #pragma unroll
    for (int r=0;r<RK;r++) acc[r]=0.f;
    for (int i=i0+il; i<i1; i+=4){
        float m = A[(size_t)i*DIMV + d] + B[(size_t)i*DIMV + d];
        #pragma unroll
        for (int r=0;r<RK;r++) acc[r] = fmaf(fac[(size_t)r*n + i], m, acc[r]);
    }
    __shared__ float red[4][RK][DIMV];
    #pragma unroll
    for (int r=0;r<RK;r++) red[il][r][d] = acc[r];
    __syncthreads();
    if (il == 0){
        #pragma unroll
        for (int r=0;r<RK;r++){
            float t = red[0][r][d] + red[1][r][d] + red[2][r][d] + red[3][r][d];
            atomicAdd(&P[r*DIMV + d], t);
        }
    }
}

// merged gathered-G + fused positive-dot. Blocks [0,512) -> U, [512,1536) -> I.
__global__ void k_gsel(const int* __restrict__ uids, const float* __restrict__ Eu0,
                       const float* __restrict__ mulsU, const float* __restrict__ P1,
                       const float* __restrict__ Eu,
                       float* __restrict__ GselU, __nv_bfloat16* __restrict__ AbfU,
                       const int* __restrict__ iids, const float* __restrict__ Ei0,
                       const float* __restrict__ mulsI, const float* __restrict__ P2,
                       const float* __restrict__ Ei,
                       float* __restrict__ GselI, __nv_bfloat16* __restrict__ AbfI,
                       float* scal){
    __shared__ float part[8];
    const int* ids; const float *base0,*muls,*P,*E; float* Gsel; __nv_bfloat16* Abf;
    int slot, i;
    int gi = blockIdx.x*256 + threadIdx.x;
    if (gi < NUID*DIMV){ ids=uids; base0=Eu0; muls=mulsU; P=P1; E=Eu; Gsel=GselU; Abf=AbfU; slot=0; i=gi; }
    else { ids=iids; base0=Ei0; muls=mulsI; P=P2; E=Ei; Gsel=GselI; Abf=AbfI; slot=1; i=gi-NUID*DIMV; }
    int w = i >> 6, d = i & 63;
    int id = ids[w];
    float s = base0[(size_t)id*DIMV + d];
    #pragma unroll
    for (int r=0;r<RK;r++) s = fmaf(muls[(size_t)id*RK + r], P[r*DIMV + d], s);
    s *= (1.0f/3.0f);
    Gsel[i] = s;
    Abf[i] = __float2bfloat16(s * 7.2134752044448170f);  // (1/T) * log2(e)
    float prod = s * E[(size_t)id*DIMV + d];
    #pragma unroll
    for (int off=16; off>0; off>>=1) prod += __shfl_xor_sync(0xffffffffu, prod, off);
    if ((threadIdx.x & 31) == 0) part[threadIdx.x >> 5] = prod;
    __syncthreads();
    if (threadIdx.x < 4){
        float dsum = part[2*threadIdx.x] + part[2*threadIdx.x+1];
        float v = fminf(fmaxf(dsum*5.0f, -5.0f), 5.0f);
        atomicAdd(&scal[slot], v);
    }
}

// merged U+I logsumexp GEMM. 1D grid: [0, NBU*16) -> U, rest -> I.
// sums[m0+r] += sum_j exp2( dot(Abf[m0+r], Ebf[j]) ). fp16x2 MUFU exp.
__global__ void __launch_bounds__(256,2) k_negmma(
        const __nv_bfloat16* __restrict__ AU, const __nv_bfloat16* __restrict__ EU,
        float* __restrict__ sumU,
        const __nv_bfloat16* __restrict__ AI, const __nv_bfloat16* __restrict__ EI,
        float* __restrict__ sumI){
    __shared__ __nv_bfloat16 As[128][72];
    __shared__ __nv_bfloat16 Bs[128][72];
    __shared__ float ls[128];
    const __nv_bfloat16 *A, *E; float* sums; int NJ, m0, jbase;
    {
        int b = blockIdx.x;
        if (b < NBU*16){ A=AU; E=EU; sums=sumU; NJ=NU; m0=(b/NBU)*128; jbase=(b%NBU)*128; }
        else { b -= NBU*16; A=AI; E=EI; sums=sumI; NJ=NI; m0=(b/NBI)*128; jbase=(b%NBI)*128; }
    }
    int tid = threadIdx.x;
    if (tid < 128) ls[tid] = 0.f;

    #pragma unroll
    for (int c = tid; c < 1024; c += 256){
        int r = c >> 3, c8 = c & 7;
        *(uint4*)&As[r][c8*8] = *(const uint4*)(A + (size_t)(m0 + r)*DIMV + c8*8);
        int j = jbase + r;
        uint4 v = make_uint4(0u,0u,0u,0u);
        if (j < NJ) v = *(const uint4*)(E + (size_t)j*DIMV + c8*8);
        *(uint4*)&Bs[r][c8*8] = v;
    }
    __syncthreads();

    int warp = tid >> 5, lane = tid & 31;
    int wm = warp >> 1, wn = warp & 1;
    int g = lane >> 2, t = lane & 3;

    float acc[2][8][4];
    #pragma unroll
    for (int mf=0;mf<2;mf++)
        #pragma unroll
        for (int nf=0;nf<8;nf++)
            #pragma unroll
            for (int q=0;q<4;q++) acc[mf][nf][q]=0.f;

    #pragma unroll
    for (int kk=0; kk<4; kk++){
        int kb = kk*16 + 2*t;
        unsigned a[2][4], b[8][2];
        #pragma unroll
        for (int mf=0; mf<2; mf++){
            int r = wm*32 + mf*16 + g;
            a[mf][0] = *(const unsigned*)&As[r  ][kb  ];
            a[mf][1] = *(const unsigned*)&As[r+8][kb  ];
            a[mf][2] = *(const unsigned*)&As[r  ][kb+8];
            a[mf][3] = *(const unsigned*)&As[r+8][kb+8];
        }
        #pragma unroll
        for (int nf=0; nf<8; nf++){
            int n = wn*64 + nf*8 + g;
            b[nf][0] = *(const unsigned*)&Bs[n][kb  ];
            b[nf][1] = *(const unsigned*)&Bs[n][kb+8];
        }
        #pragma unroll
        for (int mf=0; mf<2; mf++)
            #pragma unroll
            for (int nf=0; nf<8; nf++)
                asm volatile(
                    "mma.sync.aligned.m16n8k16.row.col.f32.bf16.bf16.f32 "
                    "{%0,%1,%2,%3}, {%4,%5,%6,%7}, {%8,%9}, {%0,%1,%2,%3};"
                    : "+f"(acc[mf][nf][0]), "+f"(acc[mf][nf][1]),
                      "+f"(acc[mf][nf][2]), "+f"(acc[mf][nf][3])
                    : "r"(a[mf][0]), "r"(a[mf][1]), "r"(a[mf][2]), "r"(a[mf][3]),
                      "r"(b[nf][0]), "r"(b[nf][1]));
    }

    // epilogue: fp16x2 exp2 (one MUFU per 2 values) + masked sum per row
    #pragma unroll
    for (int mf=0; mf<2; mf++){
        float s0 = 0.f, s1 = 0.f;
        #pragma unroll
        for (int nf=0; nf<8; nf++){
            int jc = jbase + wn*64 + nf*8 + 2*t;
            bool v0 = jc < NJ, v1 = (jc+1) < NJ;
            __half2 e0 = h2exp2(__floats2half2_rn(acc[mf][nf][0], acc[mf][nf][1]));
            __half2 e1 = h2exp2(__floats2half2_rn(acc[mf][nf][2], acc[mf][nf][3]));
            float2 f0 = __half22float2(e0);
            float2 f1 = __half22float2(e1);
            s0 += (v0 ? f0.x : 0.f) + (v1 ? f0.y : 0.f);
            s1 += (v0 ? f1.x : 0.f) + (v1 ? f1.y : 0.f);
        }
        s0 += __shfl_xor_sync(0xffffffffu, s0, 1);
        s0 += __shfl_xor_sync(0xffffffffu, s0, 2);
        s1 += __shfl_xor_sync(0xffffffffu, s1, 1);
        s1 += __shfl_xor_sync(0xffffffffu, s1, 2);
        if (t == 0){
            int rl = wm*32 + mf*16 + g;
            atomicAdd(&ls[rl],   s0);
            atomicAdd(&ls[rl+8], s1);
        }
    }
    __syncthreads();
    if (tid < 128) atomicAdd(&sums[m0 + tid], ls[tid]);
}

__global__ void k_loss(const float* __restrict__ sumU, const float* __restrict__ sumI,
                       const float* __restrict__ scal, float* outp){
    __shared__ float sh[256];
    int tid = threadIdx.x;
    float acc = 0.f;
    for (int k=tid; k<NUID; k+=256) acc += logf(sumU[k]) * (1.0f/NUID);
    for (int k=tid; k<NIID; k+=256) acc += logf(sumI[k]) * (1.0f/NIID);
    sh[tid] = acc;
    __syncthreads();
    for (int off=128; off>0; off>>=1){
        if (tid < off) sh[tid] += sh[tid+off];
        __syncthreads();
    }
    if (tid == 0){
        float neg = sh[0];
        float pos = scal[0]*(1.0f/NUID) + scal[1]*(1.0f/NIID);
        outp[0] = (neg - pos) * 4.0f;
    }
}

// ---------------- launcher ----------------
extern "C" void kernel_launch(void* const* d_in, const int* in_sizes, int n_in,
                              void* d_out, int out_size){
    const float* user_emb     = (const float*)d_in[0];
    const float* item_emb     = (const float*)d_in[1];
    const float* user_emb_pre = (const float*)d_in[2];
    const float* item_emb_pre = (const float*)d_in[3];
    const float* img_item     = (const float*)d_in[4];
    const float* txt_item     = (const float*)d_in[5];
    const float* img_user     = (const float*)d_in[6];
    const float* txt_user     = (const float*)d_in[7];
    const int*   arows        = (const int*)d_in[8];
    const int*   acols        = (const int*)d_in[9];
    const float* avals        = (const float*)d_in[10];
    const float* ut           = (const float*)d_in[11];
    const float* vt           = (const float*)d_in[12];
    const float* u_mul_s      = (const float*)d_in[13];
    const float* v_mul_s      = (const float*)d_in[14];
    const int*   uids         = (const int*)d_in[15];
    const int*   iids         = (const int*)d_in[16];
    float* out = (float*)d_out;

    float *Eu0,*Ei0,*Zu1,*Zi1,*Eu,*Ei,*GselU,*GselI,*P1,*P2,*sumU,*sumI,*scal;
    __nv_bfloat16 *E0bfU,*E0bfI,*Z1bfU,*Z1bfI,*EbfU,*EbfI,*AbfU,*AbfI;
    int *rcnt,*rbase,*ccnt,*cbase,*bsU,*bsI;
    int2 *redge,*cedge;
    cudaGetSymbolAddress((void**)&Eu0,  g_Eu0);
    cudaGetSymbolAddress((void**)&Ei0,  g_Ei0);
    cudaGetSymbolAddress((void**)&Zu1,  g_Zu1);
    cudaGetSymbolAddress((void**)&Zi1,  g_Zi1);
    cudaGetSymbolAddress((void**)&Eu,   g_Eu);
    cudaGetSymbolAddress((void**)&Ei,   g_Ei);
    cudaGetSymbolAddress((void**)&E0bfU,g_E0bfU);
    cudaGetSymbolAddress((void**)&E0bfI,g_E0bfI);
    cudaGetSymbolAddress((void**)&Z1bfU,g_Z1bfU);
    cudaGetSymbolAddress((void**)&Z1bfI,g_Z1bfI);
    cudaGetSymbolAddress((void**)&EbfU, g_EbfU);
    cudaGetSymbolAddress((void**)&EbfI, g_EbfI);
    cudaGetSymbolAddress((void**)&GselU,g_GselU);
    cudaGetSymbolAddress((void**)&GselI,g_GselI);
    cudaGetSymbolAddress((void**)&AbfU, g_AbfU);
    cudaGetSymbolAddress((void**)&AbfI, g_AbfI);
    cudaGetSymbolAddress((void**)&P1,   g_P1);
    cudaGetSymbolAddress((void**)&P2,   g_P2);
    cudaGetSymbolAddress((void**)&sumU, g_sumU);
    cudaGetSymbolAddress((void**)&sumI, g_sumI);
    cudaGetSymbolAddress((void**)&scal, g_scal);
    cudaGetSymbolAddress((void**)&rcnt, g_rcnt);
    cudaGetSymbolAddress((void**)&rbase,g_rbase);
    cudaGetSymbolAddress((void**)&ccnt, g_ccnt);
    cudaGetSymbolAddress((void**)&cbase,g_cbase);
    cudaGetSymbolAddress((void**)&redge,g_redge);
    cudaGetSymbolAddress((void**)&cedge,g_cedge);
    cudaGetSymbolAddress((void**)&bsU,  g_bsU);
    cudaGetSymbolAddress((void**)&bsI,  g_bsI);

    // 1: init
    k_setup<<<((NU+NI)*16+255)/256, 256>>>((const float4*)user_emb,(const float4*)user_emb_pre,
                                           (const float4*)item_emb,(const float4*)item_emb_pre,
                                           (float4*)Eu0,(float4*)Ei0,
                                           (uint2*)E0bfU,(uint2*)E0bfI,
                                           rcnt,ccnt,P1,P2,sumU,sumI,scal);
    // 2: degree count
    k_count<<<(NNZE+255)/256, 256>>>(arows, acols, rcnt, ccnt);
    // 3-5: fused scans
    k_scanb<<<147, 1024>>>(rcnt, rbase, bsU, ccnt, cbase, bsI);
    k_scant<<<1, 256>>>(bsU, bsI);
    k_scana<<<147, 1024>>>(rbase, bsU, cbase, bsI);
    // 6: scatter (destructive: bases advance to row ends)
    k_scatter<<<(NNZE+255)/256, 256>>>(arows,acols,avals, rbase,redge, cbase,cedge);

    // 7: GNN layer 1 merged (U rows then I rows)
    {
        SpArgs au = { rbase, rcnt, redge, E0bfI, nullptr, nullptr, 1.0f,
                      Zu1, Z1bfU, nullptr, nullptr, nullptr, NU };
        SpArgs ai = { cbase, ccnt, cedge, E0bfU, nullptr, nullptr, 1.0f,
                      Zi1, Z1bfI, nullptr, nullptr, nullptr, NI };
        k_spmm<<<(NU+NI)/16, 256>>>(au, ai);
    }
    // 8: GNN layer 2 merged + averaging + fused output epilogue
    {
        SpArgs au = { rbase, rcnt, redge, Z1bfI, Eu0, Zu1, 1.0f/3.0f,
                      Eu, EbfU, img_user, txt_user, out, NU };
        SpArgs ai = { cbase, ccnt, cedge, Z1bfU, Ei0, Zi1, 1.0f/3.0f,
                      Ei, EbfI, img_item, txt_item, out + (size_t)NU*DIMV, NI };
        k_spmm<<<(NU+NI)/16, 256>>>(au, ai);
    }

    // 9: merged low-rank
    k_lowrank<<<256, 256>>>(vt, Ei0, Zi1, P1, ut, Eu0, Zu1, P2);
    // 10: merged gsel + positive-dot
    k_gsel<<<(NUID+NIID)*DIMV/256, 256>>>(uids, Eu0, u_mul_s, P1, Eu, GselU, AbfU,
                                          iids, Ei0, v_mul_s, P2, Ei, GselI, AbfI, scal);

    // 11: merged tensor-core logsumexp GEMM
    k_negmma<<<NBU*16 + NBI*32, 256>>>(AbfU, EbfU, sumU, AbfI, EbfI, sumI);

    // 12: loss
    k_loss<<<1, 256>>>(sumU, sumI, scal, out + (size_t)(NU+NI)*DIMV);
}

// round 13
// speedup vs baseline: 1.0527x; 1.0527x over previous
#include <cuda_runtime.h>
#include <cuda_bf16.h>
#include <cuda_fp16.h>
#include <math.h>

#define NU 100000
#define NI 50000
#define DIMV 64
#define RK 5
#define NNZE 2000000
#define NUID 2048
#define NIID 4096
#define JT_U 782   // ceil(NU/128)
#define JT_I 391   // ceil(NI/128)
#define JPC 98     // j-tiles per chunk (U: 8 chunks, I: 4 chunks)

// ---------------- device scratch (no allocations allowed) ----------------
__device__ __align__(16) float g_Eu0[NU*DIMV];
__device__ __align__(16) float g_Ei0[NI*DIMV];
__device__ __align__(16) float g_Zu1[NU*DIMV];
__device__ __align__(16) float g_Zi1[NI*DIMV];
__device__ __align__(16) float g_Eu [NU*DIMV];
__device__ __align__(16) float g_Ei [NI*DIMV];
__device__ __align__(16) __nv_bfloat16 g_E0bfU[NU*DIMV];
__device__ __align__(16) __nv_bfloat16 g_E0bfI[NI*DIMV];
__device__ __align__(16) __nv_bfloat16 g_Z1bfU[NU*DIMV];
__device__ __align__(16) __nv_bfloat16 g_Z1bfI[NI*DIMV];
__device__ __align__(16) __nv_bfloat16 g_EbfU[NU*DIMV];
__device__ __align__(16) __nv_bfloat16 g_EbfI[NI*DIMV];
__device__ __align__(16) float g_GselU[NUID*DIMV];
__device__ __align__(16) float g_GselI[NIID*DIMV];
__device__ __align__(16) __nv_bfloat16 g_AbfU[NUID*DIMV];
__device__ __align__(16) __nv_bfloat16 g_AbfI[NIID*DIMV];
__device__ float g_P1[RK*DIMV];
__device__ float g_P2[RK*DIMV];
__device__ int   g_rcnt[NU];
__device__ int   g_rbase[NU];
__device__ int   g_ccnt[NI];
__device__ int   g_cbase[NI];
__device__ __align__(16) int2 g_redge[NNZE];   // (col, val_bits)
__device__ __align__(16) int2 g_cedge[NNZE];   // (row, val_bits)
__device__ int   g_bsU[128];
__device__ int   g_bsI[128];
__device__ float g_sumU[NUID];
__device__ float g_sumI[NIID];
__device__ float g_scal[8];

__device__ __forceinline__ uint2 pack_bf4(float4 v){
    __nv_bfloat162 p0 = __floats2bfloat162_rn(v.x, v.y);
    __nv_bfloat162 p1 = __floats2bfloat162_rn(v.z, v.w);
    uint2 r;
    r.x = *(unsigned*)&p0;
    r.y = *(unsigned*)&p1;
    return r;
}

// ---------------- kernels ----------------

// fused zero + E0 init (fp32 + bf16 copies)
__global__ void k_setup(const float4* __restrict__ ue, const float4* __restrict__ uep,
                        const float4* __restrict__ ie, const float4* __restrict__ iep,
                        float4* __restrict__ Eu0, float4* __restrict__ Ei0,
                        uint2* __restrict__ E0bfU, uint2* __restrict__ E0bfI,
                        int* rcnt,int* ccnt,
                        float* P1,float* P2,float* sumU,float* sumI,float* scal){
    int i = blockIdx.x*256 + threadIdx.x;
    if (i < NU*16){
        float4 a = ue[i], b = uep[i];
        float4 s = make_float4(a.x+b.x, a.y+b.y, a.z+b.z, a.w+b.w);
        Eu0[i] = s;
        E0bfU[i] = pack_bf4(s);
    } else if (i < (NU+NI)*16){
        int k = i - NU*16;
        float4 a = ie[k], b = iep[k];
        float4 s = make_float4(a.x+b.x, a.y+b.y, a.z+b.z, a.w+b.w);
        Ei0[k] = s;
        E0bfI[k] = pack_bf4(s);
    }
    if (i < NU) rcnt[i]=0;
    if (i < NI) ccnt[i]=0;
    if (i < NUID) sumU[i]=0.f;
    if (i < NIID) sumI[i]=0.f;
    if (i < RK*DIMV){ P1[i]=0.f; P2[i]=0.f; }
    if (i < 8) scal[i]=0.f;
}

__global__ void k_count(const int* __restrict__ rows, const int* __restrict__ cols,
                        int* rcnt, int* ccnt){
    int e = blockIdx.x*256 + threadIdx.x;
    if (e < NNZE){
        atomicAdd(&rcnt[rows[e]], 1);
        atomicAdd(&ccnt[cols[e]], 1);
    }
}

// fused U/I block scan: blocks 0..97 -> rcnt, 98..146 -> ccnt
__global__ void k_scanb(const int* __restrict__ rcnt, int* rbase, int* bsU,
                        const int* __restrict__ ccnt, int* cbase, int* bsI){
    __shared__ int sh[1024];
    const int* cnt; int* base; int* bsums; int n, b;
    if (blockIdx.x < 98){ cnt=rcnt; base=rbase; bsums=bsU; n=NU; b=blockIdx.x; }
    else                { cnt=ccnt; base=cbase; bsums=bsI; n=NI; b=blockIdx.x-98; }
    int i = b*1024 + threadIdx.x;
    int v = (i < n) ? cnt[i] : 0;
    sh[threadIdx.x] = v;
    __syncthreads();
    for (int off=1; off<1024; off<<=1){
        int t = (threadIdx.x >= off) ? sh[threadIdx.x-off] : 0;
        __syncthreads();
        sh[threadIdx.x] += t;
        __syncthreads();
    }
    if (i < n) base[i] = sh[threadIdx.x] - v;
    if (threadIdx.x == 1023) bsums[b] = sh[1023];
}

// fused top scan: threads 0..127 scan bsU(98), 128..255 scan bsI(49)
__global__ void k_scant(int* bsU, int* bsI){
    __shared__ int sh[256];
    int tid = threadIdx.x;
    int seg = tid >> 7, l = tid & 127;
    int nb = seg ? 49 : 98;
    int* arr = seg ? bsI : bsU;
    int v = (l < nb) ? arr[l] : 0;
    sh[tid] = v;
    __syncthreads();
    for (int off=1; off<128; off<<=1){
        int t = (l >= off) ? sh[tid-off] : 0;
        __syncthreads();
        sh[tid] += t;
        __syncthreads();
    }
    if (l < nb) arr[l] = sh[tid] - v;
}

__global__ void k_scana(int* rbase, const int* __restrict__ bsU,
                        int* cbase, const int* __restrict__ bsI){
    int* base; const int* bsums; int n, b;
    if (blockIdx.x < 98){ base=rbase; bsums=bsU; n=NU; b=blockIdx.x; }
    else                { base=cbase; bsums=bsI; n=NI; b=blockIdx.x-98; }
    int i = b*1024 + threadIdx.x;
    if (i < n) base[i] += bsums[b];
}

// destructive scatter: after this, rbase[r] = row_end (= start + cnt)
__global__ void k_scatter(const int* __restrict__ rows, const int* __restrict__ cols,
                          const float* __restrict__ vals,
                          int* rbase, int2* redge, int* cbase, int2* cedge){
    int e = blockIdx.x*256 + threadIdx.x;
    if (e < NNZE){
        int r = rows[e], c = cols[e];
        int vb = __float_as_int(vals[e]);
        int pr = atomicAdd(&rbase[r], 1);
        redge[pr] = make_int2(c, vb);
        int pc = atomicAdd(&cbase[c], 1);
        cedge[pc] = make_int2(r, vb);
    }
}

// gather-style SpMM with bf16 source rows (fp32 accumulation).
// Edge handling: each 16-lane group loads 16 edges coalesced, shfl-broadcasts
// each -> 16 independent row-gathers in flight.
__global__ void k_spmm(const int* __restrict__ base, const int* __restrict__ cnt,
                       const int2* __restrict__ edges,
                       const __nv_bfloat16* __restrict__ srcbf,
                       const float* __restrict__ add0, const float* __restrict__ add1,
                       float scale, float* __restrict__ dst,
                       __nv_bfloat16* __restrict__ bdst,
                       const float* __restrict__ img, const float* __restrict__ txt,
                       float* __restrict__ outp, int nrows){
    int row = blockIdx.x*16 + (threadIdx.x >> 4);
    int lane = threadIdx.x & 15;
    if (row >= nrows) return;
    unsigned gmask = 0xffffu << (threadIdx.x & 16);
    int n = cnt[row];
    int s = base[row] - n;     // base was advanced to row_end by scatter
    float4 acc = make_float4(0.f,0.f,0.f,0.f);
    const uint2* s2 = (const uint2*)srcbf;
    int nb = n & ~15;
    for (int p = 0; p < nb; p += 16){
        int2 my = edges[s + p + lane];
        #pragma unroll
        for (int q=0;q<16;q++){
            int col = __shfl_sync(gmask, my.x, q, 16);
            float v = __int_as_float(__shfl_sync(gmask, my.y, q, 16));
            uint2 qv = s2[(size_t)col*16 + lane];
            float2 x = __bfloat1622float2(*(const __nv_bfloat162*)&qv.x);
            float2 y = __bfloat1622float2(*(const __nv_bfloat162*)&qv.y);
            acc.x = fmaf(v, x.x, acc.x);
            acc.y = fmaf(v, x.y, acc.y);
            acc.z = fmaf(v, y.x, acc.z);
            acc.w = fmaf(v, y.y, acc.w);
        }
    }
    int rem = n - nb;
    if (rem > 0){
        int2 my = (lane < rem) ? edges[s + nb + lane] : make_int2(0,0);
        for (int q=0;q<rem;q++){
            int col = __shfl_sync(gmask, my.x, q, 16);
            float v = __int_as_float(__shfl_sync(gmask, my.y, q, 16));
            uint2 qv = s2[(size_t)col*16 + lane];
            float2 x = __bfloat1622float2(*(const __nv_bfloat162*)&qv.x);
            float2 y = __bfloat1622float2(*(const __nv_bfloat162*)&qv.y);
            acc.x = fmaf(v, x.x, acc.x);
            acc.y = fmaf(v, x.y, acc.y);
            acc.z = fmaf(v, y.x, acc.z);
            acc.w = fmaf(v, y.y, acc.w);
        }
    }
    size_t o = (size_t)row*16 + lane;
    if (add0){ float4 a = ((const float4*)add0)[o]; acc.x+=a.x; acc.y+=a.y; acc.z+=a.z; acc.w+=a.w; }
    if (add1){ float4 a = ((const float4*)add1)[o]; acc.x+=a.x; acc.y+=a.y; acc.z+=a.z; acc.w+=a.w; }
    acc.x*=scale; acc.y*=scale; acc.z*=scale; acc.w*=scale;
    ((float4*)dst)[o] = acc;
    if (bdst) ((uint2*)bdst)[o] = pack_bf4(acc);
    if (outp){
        float4 a4 = ((const float4*)img)[o];
        float4 b4 = ((const float4*)txt)[o];
        float sa = a4.x*a4.x + a4.y*a4.y + a4.z*a4.z + a4.w*a4.w;
        float sb = b4.x*b4.x + b4.y*b4.y + b4.z*b4.z + b4.w*b4.w;
        #pragma unroll
        for (int off=8; off>0; off>>=1){
            sa += __shfl_xor_sync(gmask, sa, off, 16);
            sb += __shfl_xor_sync(gmask, sb, off, 16);
        }
        float na = fmaxf(sqrtf(sa), 1e-12f);
        float nb2 = fmaxf(sqrtf(sb), 1e-12f);
        float4 r;
        r.x = acc.x + 0.02f*(a4.x/na) + 0.02f*(b4.x/nb2);
        r.y = acc.y + 0.02f*(a4.y/na) + 0.02f*(b4.y/nb2);
        r.z = acc.z + 0.02f*(a4.z/na) + 0.02f*(b4.z/nb2);
        r.w = acc.w + 0.02f*(a4.w/na) + 0.02f*(b4.w/nb2);
        ((float4*)outp)[o] = r;
    }
}

// P[r][d] += sum_i fac[r*n+i] * (A[i][d] + B[i][d])
__global__ void k_lowrank(const float* __restrict__ fac, const float* __restrict__ A,
                          const float* __restrict__ B, float* __restrict__ P, int n){
    int d  = threadIdx.x & 63;
    int il = threadIdx.x >> 6;   // 0..3
    int chunk = (n + gridDim.x - 1) / gridDim.x;
    int i0 = blockIdx.x*chunk;
    int i1 = min(i0 + chunk, n);
    float acc[RK];
    #pragma unroll
    for (int r=0;r<RK;r++) acc[r]=0.f;
    for (int i=i0+il; i<i1; i+=4){
        float m = A[(size_t)i*DIMV + d] + B[(size_t)i*DIMV + d];
        #pragma unroll
        for (int r=0;r<RK;r++) acc[r] = fmaf(fac[(size_t)r*n + i], m, acc[r]);
    }
    __shared__ float red[4][RK][DIMV];
    #pragma unroll
    for (int r=0;r<RK;r++) red[il][r][d] = acc[r];
    __syncthreads();
    if (il == 0){
        #pragma unroll
        for (int r=0;r<RK;r++){
            float t = red[0][r][d] + red[1][r][d] + red[2][r][d] + red[3][r][d];
            atomicAdd(&P[r*DIMV + d], t);
        }
    }
}

// gathered G rows + fused positive-dot
__global__ void k_gsel(const int* __restrict__ ids, const float* __restrict__ base0,
                       const float* __restrict__ muls, const float* __restrict__ P,
                       const float* __restrict__ E,
                       float* __restrict__ Gsel, __nv_bfloat16* __restrict__ Abf,
                       float* scal, int slot, int nids){
    __shared__ float part[8];
    int i = blockIdx.x*256 + threadIdx.x;
    int w = i >> 6, d = i & 63;
    int id = ids[w];
    float s = base0[(size_t)id*DIMV + d];
    #pragma unroll
    for (int r=0;r<RK;r++) s = fmaf(muls[(size_t)id*RK + r], P[r*DIMV + d], s);
    s *= (1.0f/3.0f);
    Gsel[i] = s;
    Abf[i] = __float2bfloat16(s * 7.2134752044448170f);  // (1/T) * log2(e)
    float prod = s * E[(size_t)id*DIMV + d];
    #pragma unroll
    for (int off=16; off>0; off>>=1) prod += __shfl_xor_sync(0xffffffffu, prod, off);
    if ((threadIdx.x & 31) == 0) part[threadIdx.x >> 5] = prod;
    __syncthreads();
    if (threadIdx.x < 4){
        float dsum = part[2*threadIdx.x] + part[2*threadIdx.x+1];
        float v = fminf(fmaxf(dsum*5.0f, -5.0f), 5.0f);
        atomicAdd(&scal[slot], v);
    }
}

// merged U+I logsumexp GEMM, A-resident chunked-j.
// Blocks [0,128): U (16 m-tiles x 8 chunks of 98 j-tiles);
// blocks [128,256): I (32 m-tiles x 4 chunks of 98).
// Each block: load A tile once, loop j-tiles reloading only B; accumulate
// exp2 sums in registers; one atomic pass at the end. One wave at 2 CTA/SM.
__global__ void __launch_bounds__(256,2) k_negmma(
        const __nv_bfloat16* __restrict__ AU, const __nv_bfloat16* __restrict__ EU,
        float* __restrict__ sumU,
        const __nv_bfloat16* __restrict__ AI, const __nv_bfloat16* __restrict__ EI,
        float* __restrict__ sumI){
    __shared__ __nv_bfloat16 As[128][72];
    __shared__ __nv_bfloat16 Bs[128][72];
    __shared__ float ls[128];
    const __nv_bfloat16 *A, *E; float* sums; int NJ, m0, jt0, JT;
    {
        int b = blockIdx.x;
        if (b < 128){ A=AU; E=EU; sums=sumU; NJ=NU; m0=(b>>3)*128; jt0=(b&7)*JPC; JT=JT_U; }
        else { b -= 128; A=AI; E=EI; sums=sumI; NJ=NI; m0=(b>>2)*128; jt0=(b&3)*JPC; JT=JT_I; }
    }
    int jt1 = min(jt0 + JPC, JT);
    int tid = threadIdx.x;
    if (tid < 128) ls[tid] = 0.f;

    // load A tile once
    #pragma unroll
    for (int c = tid; c < 1024; c += 256){
        int r = c >> 3, c8 = c & 7;
        *(uint4*)&As[r][c8*8] = *(const uint4*)(A + (size_t)(m0 + r)*DIMV + c8*8);
    }

    int warp = tid >> 5, lane = tid & 31;
    int wm = warp >> 1, wn = warp & 1;
    int g = lane >> 2, t = lane & 3;

    float accs[2][2] = {{0.f,0.f},{0.f,0.f}};   // per mf: (s0, s1) across all j-tiles

    for (int jt = jt0; jt < jt1; jt++){
        int jbase = jt * 128;
        __syncthreads();    // protect Bs from previous iteration's reads (covers A stores on iter 0)
        #pragma unroll
        for (int c = tid; c < 1024; c += 256){
            int r = c >> 3, c8 = c & 7;
            int j = jbase + r;
            uint4 v = make_uint4(0u,0u,0u,0u);
            if (j < NJ) v = *(const uint4*)(E + (size_t)j*DIMV + c8*8);
            *(uint4*)&Bs[r][c8*8] = v;
        }
        __syncthreads();

        float acc[2][8][4];
        #pragma unroll
        for (int mf=0;mf<2;mf++)
            #pragma unroll
            for (int nf=0;nf<8;nf++)
                #pragma unroll
                for (int q=0;q<4;q++) acc[mf][nf][q]=0.f;

        #pragma unroll
        for (int kk=0; kk<4; kk++){
            int kb = kk*16 + 2*t;
            unsigned a[2][4], b[8][2];
            #pragma unroll
            for (int mf=0; mf<2; mf++){
                int r = wm*32 + mf*16 + g;
                a[mf][0] = *(const unsigned*)&As[r  ][kb  ];
                a[mf][1] = *(const unsigned*)&As[r+8][kb  ];
                a[mf][2] = *(const unsigned*)&As[r  ][kb+8];
                a[mf][3] = *(const unsigned*)&As[r+8][kb+8];
            }
            #pragma unroll
            for (int nf=0; nf<8; nf++){
                int n = wn*64 + nf*8 + g;
                b[nf][0] = *(const unsigned*)&Bs[n][kb  ];
                b[nf][1] = *(const unsigned*)&Bs[n][kb+8];
            }
            #pragma unroll
            for (int mf=0; mf<2; mf++)
                #pragma unroll
                for (int nf=0; nf<8; nf++)
                    asm volatile(
                        "mma.sync.aligned.m16n8k16.row.col.f32.bf16.bf16.f32 "
                        "{%0,%1,%2,%3}, {%4,%5,%6,%7}, {%8,%9}, {%0,%1,%2,%3};"
                        : "+f"(acc[mf][nf][0]), "+f"(acc[mf][nf][1]),
                          "+f"(acc[mf][nf][2]), "+f"(acc[mf][nf][3])
                        : "r"(a[mf][0]), "r"(a[mf][1]), "r"(a[mf][2]), "r"(a[mf][3]),
                          "r"(b[nf][0]), "r"(b[nf][1]));
        }

        // epilogue: fp16x2 exp2, masked, accumulate into registers
        #pragma unroll
        for (int mf=0; mf<2; mf++){
            float s0 = 0.f, s1 = 0.f;
            #pragma unroll
            for (int nf=0; nf<8; nf++){
                int jc = jbase + wn*64 + nf*8 + 2*t;
                bool v0 = jc < NJ, v1 = (jc+1) < NJ;
                __half2 e0 = h2exp2(__floats2half2_rn(acc[mf][nf][0], acc[mf][nf][1]));
                __half2 e1 = h2exp2(__floats2half2_rn(acc[mf][nf][2], acc[mf][nf][3]));
                float2 f0 = __half22float2(e0);
                float2 f1 = __half22float2(e1);
                s0 += (v0 ? f0.x : 0.f) + (v1 ? f0.y : 0.f);
                s1 += (v0 ? f1.x : 0.f) + (v1 ? f1.y : 0.f);
            }
            accs[mf][0] += s0;
            accs[mf][1] += s1;
        }
    }

    // final reduce: quad shfl + smem + one global atomic pass
    #pragma unroll
    for (int mf=0; mf<2; mf++){
        float s0 = accs[mf][0], s1 = accs[mf][1];
        s0 += __shfl_xor_sync(0xffffffffu, s0, 1);
        s0 += __shfl_xor_sync(0xffffffffu, s0, 2);
        s1 += __shfl_xor_sync(0xffffffffu, s1, 1);
        s1 += __shfl_xor_sync(0xffffffffu, s1, 2);
        if (t == 0){
            int rl = wm*32 + mf*16 + g;
            atomicAdd(&ls[rl],   s0);
            atomicAdd(&ls[rl+8], s1);
        }
    }
    __syncthreads();
    if (tid < 128) atomicAdd(&sums[m0 + tid], ls[tid]);
}

__global__ void k_loss(const float* __restrict__ sumU, const float* __restrict__ sumI,
                       const float* __restrict__ scal, float* outp){
    __shared__ float sh[256];
    int tid = threadIdx.x;
    float acc = 0.f;
    for (int k=tid; k<NUID; k+=256) acc += logf(sumU[k]) * (1.0f/NUID);
    for (int k=tid; k<NIID; k+=256) acc += logf(sumI[k]) * (1.0f/NIID);
    sh[tid] = acc;
    __syncthreads();
    for (int off=128; off>0; off>>=1){
        if (tid < off) sh[tid] += sh[tid+off];
        __syncthreads();
    }
    if (tid == 0){
        float neg = sh[0];
        float pos = scal[0]*(1.0f/NUID) + scal[1]*(1.0f/NIID);
        outp[0] = (neg - pos) * 4.0f;
    }
}

// ---------------- launcher ----------------
extern "C" void kernel_launch(void* const* d_in, const int* in_sizes, int n_in,
                              void* d_out, int out_size){
    const float* user_emb     = (const float*)d_in[0];
    const float* item_emb     = (const float*)d_in[1];
    const float* user_emb_pre = (const float*)d_in[2];
    const float* item_emb_pre = (const float*)d_in[3];
    const float* img_item     = (const float*)d_in[4];
    const float* txt_item     = (const float*)d_in[5];
    const float* img_user     = (const float*)d_in[6];
    const float* txt_user     = (const float*)d_in[7];
    const int*   arows        = (const int*)d_in[8];
    const int*   acols        = (const int*)d_in[9];
    const float* avals        = (const float*)d_in[10];
    const float* ut           = (const float*)d_in[11];
    const float* vt           = (const float*)d_in[12];
    const float* u_mul_s      = (const float*)d_in[13];
    const float* v_mul_s      = (const float*)d_in[14];
    const int*   uids         = (const int*)d_in[15];
    const int*   iids         = (const int*)d_in[16];
    float* out = (float*)d_out;

    float *Eu0,*Ei0,*Zu1,*Zi1,*Eu,*Ei,*GselU,*GselI,*P1,*P2,*sumU,*sumI,*scal;
    __nv_bfloat16 *E0bfU,*E0bfI,*Z1bfU,*Z1bfI,*EbfU,*EbfI,*AbfU,*AbfI;
    int *rcnt,*rbase,*ccnt,*cbase,*bsU,*bsI;
    int2 *redge,*cedge;
    cudaGetSymbolAddress((void**)&Eu0,  g_Eu0);
    cudaGetSymbolAddress((void**)&Ei0,  g_Ei0);
    cudaGetSymbolAddress((void**)&Zu1,  g_Zu1);
    cudaGetSymbolAddress((void**)&Zi1,  g_Zi1);
    cudaGetSymbolAddress((void**)&Eu,   g_Eu);
    cudaGetSymbolAddress((void**)&Ei,   g_Ei);
    cudaGetSymbolAddress((void**)&E0bfU,g_E0bfU);
    cudaGetSymbolAddress((void**)&E0bfI,g_E0bfI);
    cudaGetSymbolAddress((void**)&Z1bfU,g_Z1bfU);
    cudaGetSymbolAddress((void**)&Z1bfI,g_Z1bfI);
    cudaGetSymbolAddress((void**)&EbfU, g_EbfU);
    cudaGetSymbolAddress((void**)&EbfI, g_EbfI);
    cudaGetSymbolAddress((void**)&GselU,g_GselU);
    cudaGetSymbolAddress((void**)&GselI,g_GselI);
    cudaGetSymbolAddress((void**)&AbfU, g_AbfU);
    cudaGetSymbolAddress((void**)&AbfI, g_AbfI);
    cudaGetSymbolAddress((void**)&P1,   g_P1);
    cudaGetSymbolAddress((void**)&P2,   g_P2);
    cudaGetSymbolAddress((void**)&sumU, g_sumU);
    cudaGetSymbolAddress((void**)&sumI, g_sumI);
    cudaGetSymbolAddress((void**)&scal, g_scal);
    cudaGetSymbolAddress((void**)&rcnt, g_rcnt);
    cudaGetSymbolAddress((void**)&rbase,g_rbase);
    cudaGetSymbolAddress((void**)&ccnt, g_ccnt);
    cudaGetSymbolAddress((void**)&cbase,g_cbase);
    cudaGetSymbolAddress((void**)&redge,g_redge);
    cudaGetSymbolAddress((void**)&cedge,g_cedge);
    cudaGetSymbolAddress((void**)&bsU,  g_bsU);
    cudaGetSymbolAddress((void**)&bsI,  g_bsI);

    // 1: init
    k_setup<<<((NU+NI)*16+255)/256, 256>>>((const float4*)user_emb,(const float4*)user_emb_pre,
                                           (const float4*)item_emb,(const float4*)item_emb_pre,
                                           (float4*)Eu0,(float4*)Ei0,
                                           (uint2*)E0bfU,(uint2*)E0bfI,
                                           rcnt,ccnt,P1,P2,sumU,sumI,scal);
    // 2: degree count
    k_count<<<(NNZE+255)/256, 256>>>(arows, acols, rcnt, ccnt);
    // 3-5: fused scans
    k_scanb<<<147, 1024>>>(rcnt, rbase, bsU, ccnt, cbase, bsI);
    k_scant<<<1, 256>>>(bsU, bsI);
    k_scana<<<147, 1024>>>(rbase, bsU, cbase, bsI);
    // 6: scatter (destructive: bases advance to row ends)
    k_scatter<<<(NNZE+255)/256, 256>>>(arows,acols,avals, rbase,redge, cbase,cedge);

    // 7-8: GNN layer 1 (bf16 gathers, fp32 accumulation; emit bf16 Z1)
    k_spmm<<<NU/16, 256>>>(rbase,rcnt,redge, E0bfI, nullptr,nullptr, 1.0f, Zu1, Z1bfU,
                           nullptr,nullptr,nullptr, NU);
    k_spmm<<<NI/16, 256>>>(cbase,ccnt,cedge, E0bfU, nullptr,nullptr, 1.0f, Zi1, Z1bfI,
                           nullptr,nullptr,nullptr, NI);
    // 9-10: GNN layer 2 + averaging + fused output epilogue
    k_spmm<<<NU/16, 256>>>(rbase,rcnt,redge, Z1bfI, Eu0, Zu1, 1.0f/3.0f, Eu, EbfU,
                           img_user, txt_user, out, NU);
    k_spmm<<<NI/16, 256>>>(cbase,ccnt,cedge, Z1bfU, Ei0, Zi1, 1.0f/3.0f, Ei, EbfI,
                           img_item, txt_item, out + (size_t)NU*DIMV, NI);

    // low-rank SVD path
    k_lowrank<<<128, 256>>>(vt, Ei0, Zi1, P1, NI);
    k_lowrank<<<128, 256>>>(ut, Eu0, Zu1, P2, NU);
    k_gsel<<<(NUID*DIMV)/256, 256>>>(uids, Eu0, u_mul_s, P1, Eu, GselU, AbfU, scal, 0, NUID);
    k_gsel<<<(NIID*DIMV)/256, 256>>>(iids, Ei0, v_mul_s, P2, Ei, GselI, AbfI, scal, 1, NIID);

    // merged tensor-core logsumexp GEMM (A-resident, chunked-j, one wave)
    k_negmma<<<256, 256>>>(AbfU, EbfU, sumU, AbfI, EbfI, sumI);

    k_loss<<<1, 256>>>(sumU, sumI, scal, out + (size_t)(NU+NI)*DIMV);
}